// round 15
// baseline (speedup 1.0000x reference)
#include <cuda_runtime.h>
#include <math.h>

#define L 256
#define D 300
#define D4 75          // D/4
#define S 16
#define KK 16
#define C 7
#define NS 48          // 3*S
#define DH 150         // D/2
#define TM 4           // row tile for 300-wide GEMMs
#define TMF 4          // row tile for fuse GEMM

// ---------------- scratch (device globals; no allocation) ----------------
__device__ float g_P0[L*D];
__device__ float g_P1[L*D];
__device__ float g_Q[L*D];
__device__ float g_Kb[L*D];
__device__ float g_VO0[L*D];
__device__ float g_VO1[L*D];
__device__ float g_Wvo[2][D*D];
__device__ float g_hidden[L*D];
__device__ float g_relatt[L*D];
__device__ float g_h1p[3][L*D];
__device__ float g_norm[L];
__device__ float g_nodes[L*NS*D];   // 14.7 MB
__device__ float g_score[L*NS];
__device__ int   g_nodemask[L*NS];
__device__ float g_sym[L*D];

__device__ __forceinline__ float warp_sum(float v) {
    #pragma unroll
    for (int o = 16; o; o >>= 1) v += __shfl_down_sync(0xffffffffu, v, o);
    return v;
}
__device__ __forceinline__ float warp_max(float v) {
    #pragma unroll
    for (int o = 16; o; o >>= 1) v = fmaxf(v, __shfl_xor_sync(0xffffffffu, v, o));
    return v;
}
__device__ __forceinline__ float warp_sum_x(float v) {
    #pragma unroll
    for (int o = 16; o; o >>= 1) v += __shfl_xor_sync(0xffffffffu, v, o);
    return v;
}
__device__ __forceinline__ float dot4(float4 a, float4 b) {
    return fmaf(a.x, b.x, fmaf(a.y, b.y, fmaf(a.z, b.z, a.w*b.w)));
}

// ---------------- K0: Wvo_h = Wv_h @ Wo_h  (300x150x300, per head) -------
__global__ void __launch_bounds__(320) wvo_kernel(const float* __restrict__ Wv,
                                                  const float* __restrict__ Wo) {
    int tile = blockIdx.x, h = blockIdx.y, j = threadIdx.x;
    int r0 = tile * TM;
    __shared__ float xs[TM][DH];
    for (int i = threadIdx.x; i < TM*DH; i += blockDim.x) {
        int r = i / DH, d = i - r*DH;
        int row = r0 + r;
        xs[r][d] = (row < D) ? Wv[row*D + h*DH + d] : 0.f;
    }
    __syncthreads();
    if (j >= D) return;
    float acc[TM];
    #pragma unroll
    for (int r = 0; r < TM; r++) acc[r] = 0.f;
    #pragma unroll 8
    for (int d = 0; d < DH; d++) {
        float w = Wo[(h*DH + d)*D + j];
        #pragma unroll
        for (int r = 0; r < TM; r++) acc[r] = fmaf(xs[r][d], w, acc[r]);
    }
    #pragma unroll
    for (int r = 0; r < TM; r++)
        if (r0 + r < D) g_Wvo[h][(r0 + r)*D + j] = acc[r];
}

// ---------------- K1: seven GEMMs out = utt @ W, TM=4 rows, 448 blocks ---
__global__ void __launch_bounds__(320) gemm7_kernel(const float* __restrict__ x,
                             const float* __restrict__ Wbasis,
                             const float* __restrict__ Wself,
                             const float* __restrict__ brgcn,
                             const float* __restrict__ Wq,
                             const float* __restrict__ Wk) {
    int tile = blockIdx.x, m = blockIdx.y, j = threadIdx.x;
    int l0 = tile * TM;
    __shared__ float xs[TM][D];
    for (int i = threadIdx.x; i < TM*D; i += blockDim.x) {
        int r = i / D, d = i - r*D;
        xs[r][d] = x[(l0 + r)*D + d];
    }
    __syncthreads();
    if (j >= D) return;
    const float* W; float* out;
    switch (m) {
        case 0: W = Wbasis;        out = g_P0;     break;
        case 1: W = Wbasis + D*D;  out = g_P1;     break;
        case 2: W = Wself;         out = g_hidden; break;
        case 3: W = Wq;            out = g_Q;      break;
        case 4: W = Wk;            out = g_Kb;     break;
        case 5: W = g_Wvo[0];      out = g_VO0;    break;
        default:W = g_Wvo[1];      out = g_VO1;    break;
    }
    float acc[TM];
    #pragma unroll
    for (int r = 0; r < TM; r++) acc[r] = 0.f;
    #pragma unroll 8
    for (int k = 0; k < D; k++) {
        float w = W[k*D + j];
        #pragma unroll
        for (int r = 0; r < TM; r++) acc[r] = fmaf(xs[r][k], w, acc[r]);
    }
    float b = (m == 2) ? brgcn[j] : 0.f;
    #pragma unroll
    for (int r = 0; r < TM; r++) out[(l0 + r)*D + j] = acc[r] + b;
}

// ---------------- K2: RGCN edge scatter via basis decomposition ----------
__global__ void edge_kernel(const int* __restrict__ src,
                            const int* __restrict__ dst,
                            const int* __restrict__ etype,
                            const float* __restrict__ comp) {
    int e = blockIdx.x, j = threadIdx.x;
    if (j >= D) return;
    int r = etype[e];
    float c0 = comp[2*r], c1 = comp[2*r + 1];
    int s = src[e], d = dst[e];
    float v = fmaf(c0, g_P0[s*D + j], c1 * g_P1[s*D + j]);
    atomicAdd(&g_hidden[d*D + j], v);
}

// ---------------- K3: windowed attn -> relatt directly (+ norms) ---------
__global__ void attn_kernel() {
    int l = blockIdx.x;
    int tid = threadIdx.x, warp = tid >> 5, lane = tid & 31;   // 192 thr
    __shared__ float lg[2][3];
    __shared__ float p[2][3];
    __shared__ float red[6];
    int w0 = (l == 0) ? 0 : l - 1;
    int w2 = (l == L-1) ? L-1 : l + 1;
    int win[3] = {w0, l, w2};
    if (warp < 6) {
        int h = warp / 3, j = warp % 3;
        const float2* q = (const float2*)(g_Q  + l*D       + h*DH);   // 75 f2
        const float2* k = (const float2*)(g_Kb + win[j]*D  + h*DH);
        int d0 = lane, d1 = lane + 32, d2 = lane + 64;
        bool p2 = (d2 < D4);   // 75 float2 per head-row
        float2 qa = q[d0], qb = q[d1];
        float2 ka = k[d0], kb = k[d1];
        float2 qc = p2 ? q[d2] : make_float2(0.f, 0.f);
        float2 kc = p2 ? k[d2] : make_float2(0.f, 0.f);
        float acc = fmaf(qa.x, ka.x, qa.y*ka.y)
                  + fmaf(qb.x, kb.x, qb.y*kb.y)
                  + fmaf(qc.x, kc.x, qc.y*kc.y);
        acc = warp_sum(acc);
        if (lane == 0) lg[h][j] = acc * 0.08164965809277261f;  // 1/sqrt(150)
    }
    __syncthreads();
    if (tid < 2) {
        float m = fmaxf(lg[tid][0], fmaxf(lg[tid][1], lg[tid][2]));
        float e0 = expf(lg[tid][0]-m), e1 = expf(lg[tid][1]-m), e2 = expf(lg[tid][2]-m);
        float inv = 1.f / (e0 + e1 + e2);
        p[tid][0] = e0*inv; p[tid][1] = e1*inv; p[tid][2] = e2*inv;
    }
    __syncthreads();
    float nrm = 0.f;
    for (int d = tid; d < D; d += 192) {
        float acc = 0.f;
        #pragma unroll
        for (int j = 0; j < 3; j++) {
            acc = fmaf(p[0][j], g_VO0[win[j]*D + d], acc);
            acc = fmaf(p[1][j], g_VO1[win[j]*D + d], acc);
        }
        g_relatt[l*D + d] = acc;
        nrm = fmaf(acc, acc, nrm);
    }
    nrm = warp_sum(nrm);
    if (lane == 0) red[warp] = nrm;
    __syncthreads();
    if (tid == 0) {
        float t = red[0] + red[1] + red[2] + red[3] + red[4] + red[5];
        g_norm[l] = sqrtf(t);
    }
}

// ---------------- K5: concept-graph attention ----------------------------
// front-batched 6-load gather per warp; 4 dots (du,dd,ds,dru); score fused
__global__ void __launch_bounds__(256) concept_kernel(
                               const int* __restrict__ src_ids,
                               const int* __restrict__ dst_ids,
                               const float* __restrict__ wgt,
                               const float* __restrict__ sentic,
                               const float* __restrict__ table,
                               const float* __restrict__ rvecs) {
    int bid = blockIdx.x;                 // g*L*S + l*S + s
    int g = bid / (L*S);
    int rem = bid - g*(L*S);
    int l = rem / S;
    int s = rem - l*S;
    int n = g*S + s;
    int tid = threadIdx.x;                // 256 threads, 8 warps

    __shared__ float4 sh_dst[KK][D4];
    __shared__ float4 sh_src[D4], sh_u[D4], sh_r[D4], sh_p[D4], sh_ru[D4];
    __shared__ float sh_du[KK], sh_dd[KK], sh_ds[KK], sh_dru[KK], sh_c[KK];
    __shared__ float sh_w[KK], sh_sn[KK];
    __shared__ int   sh_ids[KK];

    int src_id = src_ids[bid];
    float4* outrow = (float4*)&g_nodes[(size_t)(l*NS + n) * D];
    if (src_id < 0) {
        if (tid == 0) { g_nodemask[l*NS + n] = 0; g_score[l*NS + n] = 0.f; }
        float4 z = make_float4(0.f, 0.f, 0.f, 0.f);
        if (tid < D4) outrow[tid] = z;
        return;
    }
    if (tid == 0) g_nodemask[l*NS + n] = 1;
    if (tid < KK) sh_ids[tid] = dst_ids[(size_t)bid*KK + tid];
    if (tid >= 128 && tid < 128 + KK) sh_w[tid - 128]  = wgt[(size_t)bid*KK + tid - 128];
    if (tid >= 160 && tid < 160 + KK) sh_sn[tid - 160] = sentic[(size_t)bid*KK + tid - 160];
    if (tid < D4) {
        float4 sr = ((const float4*)(table + (size_t)src_id*D))[tid];
        float4 u  = ((const float4*)(g_relatt + l*D))[tid];
        float4 rr = ((const float4*)(rvecs + g*D))[tid];
        sh_src[tid] = sr; sh_u[tid] = u; sh_r[tid] = rr;
        sh_p[tid]  = make_float4(sr.x*rr.x, sr.y*rr.y, sr.z*rr.z, sr.w*rr.w);
        sh_ru[tid] = make_float4(rr.x*u.x,  rr.y*u.y,  rr.z*u.z,  rr.w*u.w);
    }
    __syncthreads();

    int warp = tid >> 5, lane = tid & 31;
    {
        int k0 = warp, k1 = warp + 8;
        int id0 = sh_ids[k0], id1 = sh_ids[k1];
        const float4* row0 = (const float4*)(table + (size_t)(id0 < 0 ? 0 : id0)*D);
        const float4* row1 = (const float4*)(table + (size_t)(id1 < 0 ? 0 : id1)*D);
        int d0 = lane, d1 = lane + 32, d2 = lane + 64;
        bool pp = (d2 < D4);
        float4 z = make_float4(0.f, 0.f, 0.f, 0.f);
        // front-batched loads: 6 independent LDG.128 in flight
        float4 v00 = (id0 >= 0) ? row0[d0] : z;
        float4 v01 = (id0 >= 0) ? row0[d1] : z;
        float4 v02 = (id0 >= 0 && pp) ? row0[d2] : z;
        float4 v10 = (id1 >= 0) ? row1[d0] : z;
        float4 v11 = (id1 >= 0) ? row1[d1] : z;
        float4 v12 = (id1 >= 0 && pp) ? row1[d2] : z;
        sh_dst[k0][d0] = v00; sh_dst[k0][d1] = v01;
        sh_dst[k1][d0] = v10; sh_dst[k1][d1] = v11;
        if (pp) { sh_dst[k0][d2] = v02; sh_dst[k1][d2] = v12; }
        float4 u0 = sh_u[d0],  u1 = sh_u[d1];
        float4 p0 = sh_p[d0],  p1 = sh_p[d1];
        float4 r0 = sh_ru[d0], r1 = sh_ru[d1];
        float du0 = dot4(u0, v00) + dot4(u1, v01);
        float dd0 = dot4(v00, v00) + dot4(v01, v01);
        float ds0 = dot4(p0, v00) + dot4(p1, v01);
        float dr0 = dot4(r0, v00) + dot4(r1, v01);
        float du1 = dot4(u0, v10) + dot4(u1, v11);
        float dd1 = dot4(v10, v10) + dot4(v11, v11);
        float ds1 = dot4(p0, v10) + dot4(p1, v11);
        float dr1 = dot4(r0, v10) + dot4(r1, v11);
        if (pp) {
            float4 u2 = sh_u[d2], p2v = sh_p[d2], r2 = sh_ru[d2];
            du0 += dot4(u2, v02); dd0 += dot4(v02, v02);
            ds0 += dot4(p2v, v02); dr0 += dot4(r2, v02);
            du1 += dot4(u2, v12); dd1 += dot4(v12, v12);
            ds1 += dot4(p2v, v12); dr1 += dot4(r2, v12);
        }
        du0 = warp_sum(du0); dd0 = warp_sum(dd0); ds0 = warp_sum(ds0); dr0 = warp_sum(dr0);
        du1 = warp_sum(du1); dd1 = warp_sum(dd1); ds1 = warp_sum(ds1); dr1 = warp_sum(dr1);
        if (lane == 0) {
            sh_du[k0] = du0; sh_dd[k0] = dd0; sh_ds[k0] = ds0; sh_dru[k0] = dr0;
            sh_du[k1] = du1; sh_dd[k1] = dd1; sh_ds[k1] = ds1; sh_dru[k1] = dr1;
        }
    }
    __syncthreads();

    // warp 0: su = src.u, double softmax, fused sym-score
    if (warp == 0) {
        int d0 = lane, d1 = lane + 32, d2 = lane + 64;
        float su = dot4(sh_src[d0], sh_u[d0]) + dot4(sh_src[d1], sh_u[d1]);
        if (d2 < D4) su += dot4(sh_src[d2], sh_u[d2]);
        su = warp_sum_x(su);

        int k = lane;
        bool valid = (k < KK) && (sh_ids[k] >= 0);
        float norm_u = g_norm[l];
        float om = -1e30f;
        if (valid) {
            float cosv = fabsf(sh_du[k]) / (norm_u * sqrtf(sh_dd[k]) + 1e-8f);
            om = 0.5f*sh_w[k]*cosv + 0.5f*fabsf(sh_sn[k]);
        }
        float m1 = warp_max(om);
        float a1 = valid ? expf(om - m1) : 0.f;
        float sum1 = warp_sum_x(a1);
        a1 *= (sum1 > 0.f) ? (1.f / sum1) : 0.f;
        float sv = valid ? a1 * sh_ds[k] : -1e30f;
        float m2 = warp_max(sv);
        float a2 = valid ? expf(sv - m2) : 0.f;
        float sum2 = warp_sum_x(a2);
        float c = a1 * a2 * ((sum2 > 0.f) ? (1.f / sum2) : 0.f);
        if (k < KK) sh_c[k] = c;
        float contrib = valid ? c * sh_dru[k] : 0.f;
        float sc = warp_sum_x(contrib);
        if (lane == 0) g_score[l*NS + n] = su + sc;
    }
    __syncthreads();

    if (tid < D4) {
        float ax = 0.f, ay = 0.f, az = 0.f, aw = 0.f;
        #pragma unroll
        for (int k = 0; k < KK; k++) {
            float c = sh_c[k];
            float4 v = sh_dst[k][tid];
            ax = fmaf(c, v.x, ax); ay = fmaf(c, v.y, ay);
            az = fmaf(c, v.z, az); aw = fmaf(c, v.w, aw);
        }
        float4 sr = sh_src[tid], rr = sh_r[tid], o;
        o.x = fmaf(rr.x, ax, sr.x); o.y = fmaf(rr.y, ay, sr.y);
        o.z = fmaf(rr.z, az, sr.z); o.w = fmaf(rr.w, aw, sr.w);
        outrow[tid] = o;
    }
}

// ---------------- K6: symbolic attention (scores precomputed) ------------
__global__ void __launch_bounds__(320) sym_kernel() {
    int l = blockIdx.x, tid = threadIdx.x;   // 320 threads
    __shared__ float att[NS];
    __shared__ float s_any;
    if (tid == 0) {
        float sc[NS]; int mk[NS];
        float m = -1e30f; int anyv = 0;
        #pragma unroll 8
        for (int nn = 0; nn < NS; nn++) {
            sc[nn] = g_score[l*NS + nn];
            mk[nn] = g_nodemask[l*NS + nn];
        }
        #pragma unroll
        for (int nn = 0; nn < NS; nn++)
            if (mk[nn]) { if (sc[nn] > m) m = sc[nn]; anyv = 1; }
        float sum = 0.f;
        #pragma unroll
        for (int nn = 0; nn < NS; nn++) {
            float a = mk[nn] ? expf(sc[nn] - m) : 0.f;
            att[nn] = a; sum += a;
        }
        float inv = anyv ? (1.f / sum) : 0.f;
        #pragma unroll
        for (int nn = 0; nn < NS; nn++) att[nn] *= inv;
        s_any = anyv ? 1.f : 0.f;
    }
    __syncthreads();
    if (tid < D) {
        float acc = 0.f;
        const float* base = &g_nodes[(size_t)l*NS*D + tid];
        #pragma unroll 8
        for (int nn = 0; nn < NS; nn++)
            acc = fmaf(att[nn], base[nn*D], acc);
        g_sym[l*D + tid] = acc * s_any;
    }
}

// ---------------- K7a: fuse GEMM split-K: each z-block does one source ---
__global__ void __launch_bounds__(160) fuse1_kernel(const float* __restrict__ Wf) {
    int tile = blockIdx.x, cs = blockIdx.y, ks = blockIdx.z;
    int tid = threadIdx.x;   // 160 threads
    int l0 = tile * TMF;
    const float* srcbuf = (ks == 0) ? g_hidden : (ks == 1) ? g_relatt : g_sym;
    __shared__ float xs[TMF][D];
    for (int i = tid; i < TMF*D; i += blockDim.x) {
        int r = i / D, d = i - r*D;
        xs[r][d] = srcbuf[(l0 + r)*D + d];
    }
    __syncthreads();
    if (tid >= DH) return;
    int j = cs * DH + tid;
    const float* W = Wf + (size_t)(ks*D)*D;    // rows [ks*300, ks*300+300)
    float acc[TMF];
    #pragma unroll
    for (int r = 0; r < TMF; r++) acc[r] = 0.f;
    #pragma unroll 8
    for (int k = 0; k < D; k++) {
        float w = W[k*D + j];
        #pragma unroll
        for (int r = 0; r < TMF; r++) acc[r] = fmaf(xs[r][k], w, acc[r]);
    }
    #pragma unroll
    for (int r = 0; r < TMF; r++) g_h1p[ks][(l0 + r)*D + j] = acc[r];
}

// ---------------- K7b: combine partials + relu + logits + log_softmax ----
__global__ void fuse2_kernel(const float* __restrict__ bf,
                             const float* __restrict__ Wout,
                             const float* __restrict__ bout,
                             float* __restrict__ out) {
    int l = blockIdx.x, tid = threadIdx.x;   // 256 threads
    __shared__ float logits[C];
    __shared__ float sh_lse;
    int warp = tid >> 5, lane = tid & 31;
    if (warp < C) {
        float acc = 0.f;
        for (int j = lane; j < D; j += 32) {
            float h = g_h1p[0][l*D + j] + g_h1p[1][l*D + j] + g_h1p[2][l*D + j] + bf[j];
            h = fmaxf(h, 0.f);
            acc = fmaf(h, Wout[j*C + warp], acc);
        }
        acc = warp_sum(acc);
        if (lane == 0) logits[warp] = acc + bout[warp];
    }
    __syncthreads();
    if (tid == 0) {
        float m = logits[0];
        #pragma unroll
        for (int c = 1; c < C; c++) m = fmaxf(m, logits[c]);
        float sum = 0.f;
        #pragma unroll
        for (int c = 0; c < C; c++) sum += expf(logits[c] - m);
        sh_lse = m + logf(sum);
    }
    __syncthreads();
    if (tid < C) out[l*C + tid] = logits[tid] - sh_lse;
}

// ---------------- launch --------------------------------------------------
extern "C" void kernel_launch(void* const* d_in, const int* in_sizes, int n_in,
                              void* d_out, int out_size) {
    const float* utt    = (const float*)d_in[0];
    const int*   ssrc   = (const int*)  d_in[1];
    const int*   sdst   = (const int*)  d_in[2];
    const int*   setype = (const int*)  d_in[3];
    const int*   csrc   = (const int*)  d_in[4];
    const int*   cdst   = (const int*)  d_in[5];
    const float* cw     = (const float*)d_in[6];
    const float* cs     = (const float*)d_in[7];
    const float* table  = (const float*)d_in[8];
    const float* Wbasis = (const float*)d_in[9];
    const float* comp   = (const float*)d_in[10];
    const float* Wself  = (const float*)d_in[11];
    const float* brgcn  = (const float*)d_in[12];
    const float* Wq     = (const float*)d_in[13];
    const float* Wk     = (const float*)d_in[14];
    const float* Wv     = (const float*)d_in[15];
    const float* Wo     = (const float*)d_in[16];
    const float* rvecs  = (const float*)d_in[17];
    const float* Wf     = (const float*)d_in[18];
    const float* bf     = (const float*)d_in[19];
    const float* Wout   = (const float*)d_in[20];
    const float* bout   = (const float*)d_in[21];
    float* out = (float*)d_out;

    int n_edges = in_sizes[1];

    wvo_kernel<<<dim3((D + TM - 1)/TM, 2), 320>>>(Wv, Wo);
    gemm7_kernel<<<dim3(L/TM, 7), 320>>>(utt, Wbasis, Wself, brgcn, Wq, Wk);
    edge_kernel<<<n_edges, 300>>>(ssrc, sdst, setype, comp);
    attn_kernel<<<L, 192>>>();
    concept_kernel<<<3*L*S, 256>>>(csrc, cdst, cw, cs, table, rvecs);
    sym_kernel<<<L, 320>>>();
    fuse1_kernel<<<dim3(L/TMF, 2, 3), 160>>>(Wf);
    fuse2_kernel<<<L, 256>>>(bf, Wout, bout, out);
}